// round 8
// baseline (speedup 1.0000x reference)
#include <cuda_runtime.h>
#include <cstdint>

// out[b,f] = -( sum_w x[b,w,f] * W[f,w] + bias[f] )
// x: [512, 5, 25000] f32   W: [25000, 5] f32   bias: [25000] f32   out: [512, 25000] f32
//
// R8: persistent CTAs (608 = 4/SM x 152) + dynamic work queue.
// Item = (f-block of 1024 feats, pair of batch rows): 25 x 256 = 6400 items.
// Per item: identical memory shape to R6 (10 independent LDG.128 in flight,
// W/bias in conflict-free per-thread SMEM column, .cs on x/out).
// Work counter self-resets via a done-counter so the kernel is graph-replay
// deterministic with no extra launch.

#define F_DIM    25000
#define WS       5
#define B_DIM    512
#define B_PER    2
#define NTHREADS 256
#define F4_DIM   (F_DIM / 4)            // 6250
#define XBLKS    25                      // f-blocks of 256 float4
#define YBLKS    (B_DIM / B_PER)         // 256
#define N_ITEMS  (XBLKS * YBLKS)         // 6400
#define N_CTAS   608                     // 152 SMs x 4 CTAs

__device__ unsigned int g_counter = 0;
__device__ unsigned int g_done    = 0;

__global__ __launch_bounds__(NTHREADS, 4)
void ocsvm_kernel(const float* __restrict__ x,
                  const float* __restrict__ W,
                  const float* __restrict__ bias,
                  float* __restrict__ out) {
    // w_s[0..19][tid] = W for this thread's 4 features, w_s[20..23][tid] = -bias.
    // 4B stride across threads -> bank = tid%32: conflict-free, no syncs needed
    // (each thread touches only its own column).
    __shared__ float w_s[4 * WS + 4][NTHREADS];
    __shared__ unsigned int s_item;

    const int tid = threadIdx.x;
    int cur_xblk = -1;   // cached f-block whose W is loaded in w_s

    for (;;) {
        __syncthreads();   // previous s_item fully consumed before overwrite
        if (tid == 0) s_item = atomicAdd(&g_counter, 1u);
        __syncthreads();
        const unsigned int item = s_item;
        if (item >= N_ITEMS) break;

        // f-fastest ordering: concurrent grabs read contiguous DRAM.
        const int xblk = (int)(item % XBLKS);
        const int y    = (int)(item / XBLKS);
        const int f4   = xblk * NTHREADS + tid;
        const bool valid = (f4 < F4_DIM);
        const int f = f4 * 4;

        if (valid && xblk != cur_xblk) {
            const float4* W4 = reinterpret_cast<const float4*>(W) + (size_t)f4 * WS;
#pragma unroll
            for (int k = 0; k < WS; k++) {
                float4 q = __ldg(W4 + k);
                w_s[4 * k + 0][tid] = q.x;
                w_s[4 * k + 1][tid] = q.y;
                w_s[4 * k + 2][tid] = q.z;
                w_s[4 * k + 3][tid] = q.w;
            }
            const float4 bb = __ldg(reinterpret_cast<const float4*>(bias + f));
            w_s[20][tid] = -bb.x;
            w_s[21][tid] = -bb.y;
            w_s[22][tid] = -bb.z;
            w_s[23][tid] = -bb.w;
        }
        cur_xblk = xblk;

        if (valid) {
            const int b0 = y * B_PER;

            // All 10 streaming loads in flight before any math.
            float4 xv[B_PER][WS];
#pragma unroll
            for (int bi = 0; bi < B_PER; bi++) {
                const size_t base = (size_t)(b0 + bi) * (WS * F_DIM) + f;
#pragma unroll
                for (int wi = 0; wi < WS; wi++) {
                    xv[bi][wi] = __ldcs(reinterpret_cast<const float4*>(
                        x + base + (size_t)wi * F_DIM));
                }
            }

#pragma unroll
            for (int bi = 0; bi < B_PER; bi++) {
                float a0 = w_s[20][tid], a1 = w_s[21][tid];
                float a2 = w_s[22][tid], a3 = w_s[23][tid];
#pragma unroll
                for (int wi = 0; wi < WS; wi++) {
                    a0 = fmaf(-xv[bi][wi].x, w_s[0 * WS + wi][tid], a0);
                    a1 = fmaf(-xv[bi][wi].y, w_s[1 * WS + wi][tid], a1);
                    a2 = fmaf(-xv[bi][wi].z, w_s[2 * WS + wi][tid], a2);
                    a3 = fmaf(-xv[bi][wi].w, w_s[3 * WS + wi][tid], a3);
                }
                float4 o; o.x = a0; o.y = a1; o.z = a2; o.w = a3;
                __stcs(reinterpret_cast<float4*>(out + (size_t)(b0 + bi) * F_DIM + f), o);
            }
        }
    }

    // Last CTA to finish resets the queue for the next graph replay.
    if (tid == 0) {
        __threadfence();
        unsigned int d = atomicAdd(&g_done, 1u);
        if (d == N_CTAS - 1) {
            g_counter = 0;
            g_done = 0;
        }
    }
}

extern "C" void kernel_launch(void* const* d_in, const int* in_sizes, int n_in,
                              void* d_out, int out_size) {
    const float* x    = (const float*)d_in[0];
    const float* W    = (const float*)d_in[1];
    const float* bias = (const float*)d_in[2];
    float* out        = (float*)d_out;

    ocsvm_kernel<<<N_CTAS, NTHREADS>>>(x, W, bias, out);
}